// round 7
// baseline (speedup 1.0000x reference)
#include <cuda_runtime.h>
#include <math.h>
#include <float.h>
#include <stdint.h>

#define NPIX 131072
#define DIMC 720
#define HWSZ 32768
#define WID 256
#define KCLS 19
#define MPROT 10
#define JTOT 190
#define JPAD 192

// ---------------- device scratch (static, zero-initialized at load) ----------------
__device__ float g_cn[DIMC * NPIX];      // normalized features, layout (D, N): [d*NPIX + n]
__device__ float g_Pn[JTOT * DIMC];      // l2-normalized prototypes, row-major (190, 720)
__device__ float g_PT[DIMC * JPAD];      // transposed padded protos (720, 192); pad cols stay 0
__device__ float g_scal[3];              // sum g^2, sum g*b, sum b^2
__device__ float g_mu[NPIX], g_is[NPIX], g_sc[NPIX];
__device__ float g_S[KCLS];              // initial per-class total sums
__device__ int   g_Bk[KCLS];             // per-class pixel counts
__device__ float g_R[3 * JTOT];          // per-iteration row sums (Sigma v*b)
__device__ float g_a[JTOT];              // sinkhorn row factors
__device__ float g_b[NPIX];              // sinkhorn col factors
__device__ unsigned char g_corr[NPIX];
__device__ unsigned char g_m[NPIX];
__device__ float g_f[JTOT * DIMC];
__device__ int   g_cnt[JTOT];

// ---------------- helpers ----------------
__device__ __forceinline__ float block_reduce_256(float v, float* red) {
    int t = threadIdx.x;
    __syncthreads();           // protect red[] reuse
    red[t] = v;
    __syncthreads();
    #pragma unroll
    for (int s = 128; s > 0; s >>= 1) {
        if (t < s) red[t] += red[t + s];
        __syncthreads();
    }
    return red[0];
}

// ---------------- kernels ----------------
__global__ void k_zero() {
    int i = blockIdx.x * 256 + threadIdx.x;
    if (i < JTOT * DIMC) g_f[i] = 0.f;
    if (i < JTOT) g_cnt[i] = 0;
    if (i < 3 * JTOT) g_R[i] = 0.f;
    if (i < KCLS) { g_S[i] = 0.f; g_Bk[i] = 0; }
}

__global__ void k_prep_scal(const float* __restrict__ g, const float* __restrict__ b) {
    __shared__ float red[256];
    int t = threadIdx.x;
    float s0 = 0.f, s1 = 0.f, s2 = 0.f;
    for (int d = t; d < DIMC; d += 256) {
        float gv = g[d], bv = b[d];
        s0 += gv * gv; s1 += gv * bv; s2 += bv * bv;
    }
    float r0 = block_reduce_256(s0, red);
    float r1 = block_reduce_256(s1, red);
    float r2 = block_reduce_256(s2, red);
    if (t == 0) { g_scal[0] = r0; g_scal[1] = r1; g_scal[2] = r2; }
}

__global__ void k_prep_protos(const float* __restrict__ P) {
    __shared__ float red[256];
    int j = blockIdx.x, t = threadIdx.x;
    float ss = 0.f;
    for (int d = t; d < DIMC; d += 256) { float v = P[j * DIMC + d]; ss += v * v; }
    float nrm = sqrtf(block_reduce_256(ss, red));
    float inv = 1.f / fmaxf(nrm, 1e-12f);
    for (int d = t; d < DIMC; d += 256) {
        float v = P[j * DIMC + d] * inv;
        g_Pn[j * DIMC + d] = v;
        g_PT[d * JPAD + j] = v;
    }
}

// per-pixel layernorm stats + post-LN l2 norm scale (one coalesced pass over c)
__global__ void k_stats(const float* __restrict__ c,
                        const float* __restrict__ gam, const float* __restrict__ bet) {
    __shared__ float sg[DIMC], sb[DIMC];
    int t = threadIdx.x;
    for (int d = t; d < DIMC; d += blockDim.x) { sg[d] = gam[d]; sb[d] = bet[d]; }
    __syncthreads();
    int n = blockIdx.x * blockDim.x + t;
    int b = n >> 15, hw = n & (HWSZ - 1);
    const float* base = c + (size_t)b * DIMC * HWSZ + hw;
    float sx = 0.f, sxx = 0.f, s2x = 0.f, s2xx = 0.f, sbx = 0.f;
    for (int d = 0; d < DIMC; ++d) {
        float x = base[(size_t)d * HWSZ];
        float g = sg[d], bb = sb[d];
        float x2 = x * x;
        sx += x; sxx += x2;
        float g2 = g * g;
        s2x = fmaf(g2, x, s2x);
        s2xx = fmaf(g2, x2, s2xx);
        sbx = fmaf(g * bb, x, sbx);
    }
    float mu = sx * (1.f / DIMC);
    float var = sxx * (1.f / DIMC) - mu * mu;
    float is = 1.f / sqrtf(var + 1e-5f);
    float Sg2 = g_scal[0], Sgb = g_scal[1], Sb2 = g_scal[2];
    float lnss = is * is * (s2xx - 2.f * mu * s2x + mu * mu * Sg2)
               + 2.f * is * (sbx - mu * Sgb) + Sb2;
    lnss = fmaxf(lnss, 0.f);
    float sc = 1.f / fmaxf(sqrtf(lnss), 1e-12f);
    g_mu[n] = mu; g_is[n] = is; g_sc[n] = sc;
}

// write normalized features in (D, N) layout, float4 per thread
__global__ void k_normwrite(const float* __restrict__ c,
                            const float* __restrict__ gam, const float* __restrict__ bet) {
    int idx = blockIdx.x * blockDim.x + threadIdx.x;  // float4 index; total 720*32768
    int d = idx >> 15;             // 131072/4 = 32768 float4 per d-row
    int c4 = idx & 32767;
    int n = c4 * 4;
    int b = n >> 15, hw = n & (HWSZ - 1);
    const float4 x = *(const float4*)&c[(size_t)b * DIMC * HWSZ + (size_t)d * HWSZ + hw];
    float4 mu = *(const float4*)&g_mu[n];
    float4 is = *(const float4*)&g_is[n];
    float4 sc = *(const float4*)&g_sc[n];
    float g = __ldg(&gam[d]), bb = __ldg(&bet[d]);
    float4 o;
    o.x = ((x.x - mu.x) * is.x * g + bb) * sc.x;
    o.y = ((x.y - mu.y) * is.y * g + bb) * sc.y;
    o.z = ((x.z - mu.z) * is.z * g + bb) * sc.z;
    o.w = ((x.w - mu.w) * is.w * g + bb) * sc.w;
    *(float4*)&g_cn[(size_t)d * NPIX + n] = o;
}

// GEMM: logits(N,190) = _c(N,720) @ PT(720,192); A in (D,N) layout, 64 pixels/block
__global__ void __launch_bounds__(256) k_gemm(float* __restrict__ Cout) {
    __shared__ __align__(16) float As[16][64];
    __shared__ __align__(16) float Bs[16][192];
    int tid = threadIdx.x;
    int tx = tid & 31, ty = tid >> 5;
    int n0 = blockIdx.x * 64;
    int lrow = tid >> 4, lcol = (tid & 15) * 4;
    float acc[8][6];
    #pragma unroll
    for (int i = 0; i < 8; i++)
        #pragma unroll
        for (int j = 0; j < 6; j++) acc[i][j] = 0.f;

    for (int k0 = 0; k0 < DIMC; k0 += 16) {
        *(float4*)&As[lrow][lcol] =
            *(const float4*)&g_cn[(size_t)(k0 + lrow) * NPIX + n0 + lcol];
        #pragma unroll
        for (int o = 0; o < 3; o++)
            *(float4*)&Bs[lrow][lcol + o * 64] =
                *(const float4*)&g_PT[(k0 + lrow) * JPAD + lcol + o * 64];
        __syncthreads();
        #pragma unroll
        for (int kk = 0; kk < 16; kk++) {
            float4 a0 = *(const float4*)&As[kk][ty * 8];
            float4 a1 = *(const float4*)&As[kk][ty * 8 + 4];
            float av[8] = {a0.x, a0.y, a0.z, a0.w, a1.x, a1.y, a1.z, a1.w};
            float2 b0 = *(const float2*)&Bs[kk][tx * 6];
            float2 b1 = *(const float2*)&Bs[kk][tx * 6 + 2];
            float2 b2 = *(const float2*)&Bs[kk][tx * 6 + 4];
            float bv[6] = {b0.x, b0.y, b1.x, b1.y, b2.x, b2.y};
            #pragma unroll
            for (int i = 0; i < 8; i++)
                #pragma unroll
                for (int j = 0; j < 6; j++)
                    acc[i][j] = fmaf(av[i], bv[j], acc[i][j]);
        }
        __syncthreads();
    }
    int j0 = tx * 6;
    #pragma unroll
    for (int i = 0; i < 8; i++) {
        int n = n0 + ty * 8 + i;
        #pragma unroll
        for (int j = 0; j < 6; j++)
            if (j0 + j < JTOT) Cout[(size_t)n * JTOT + j0 + j] = acc[i][j];
    }
}

// per-pixel head: class maxes -> layernorm(19) -> out_seg + pred/correct. warp per pixel.
__global__ void k_head(const float* __restrict__ logits, const int* __restrict__ gt,
                       const float* __restrict__ mg, const float* __restrict__ mb,
                       float* __restrict__ out_seg) {
    __shared__ float rows[8][JPAD];
    int warp = threadIdx.x >> 5, lane = threadIdx.x & 31;
    int n = blockIdx.x * 8 + warp;
    const float* lr = logits + (size_t)n * JTOT;
    #pragma unroll
    for (int i = 0; i < 6; i++) {
        int j = lane + 32 * i;
        if (j < JTOT) rows[warp][j] = lr[j];
    }
    __syncwarp();
    float mx = -FLT_MAX;
    if (lane < KCLS) {
        #pragma unroll
        for (int m = 0; m < MPROT; m++) mx = fmaxf(mx, rows[warp][lane * MPROT + m]);
    }
    float xv = (lane < KCLS) ? mx : 0.f;
    float s = xv, s2 = xv * xv;
    #pragma unroll
    for (int off = 16; off; off >>= 1) {
        s  += __shfl_xor_sync(0xffffffffu, s, off);
        s2 += __shfl_xor_sync(0xffffffffu, s2, off);
    }
    float mu = s * (1.f / KCLS);
    float var = s2 * (1.f / KCLS) - mu * mu;
    float isd = 1.f / sqrtf(var + 1e-5f);
    float o = -FLT_MAX;
    if (lane < KCLS) {
        o = (mx - mu) * isd * __ldg(&mg[lane]) + __ldg(&mb[lane]);
        int b = n >> 15, h = (n >> 8) & 127, w = n & 255;
        out_seg[(((size_t)b * KCLS + lane) * 128 + h) * WID + w] = o;
    }
    float bv = o; int bi = lane;
    #pragma unroll
    for (int off = 16; off; off >>= 1) {
        float ov = __shfl_xor_sync(0xffffffffu, bv, off);
        int   oi = __shfl_xor_sync(0xffffffffu, bi, off);
        if (ov > bv || (ov == bv && oi < bi)) { bv = ov; bi = oi; }
    }
    if (lane == 0) g_corr[n] = (bi == gt[n]) ? 1 : 0;
}

// sinkhorn init: per-class S (global sum), Bk (count), R[0] (Sigma v, b0=1); set b=1
__global__ void k_sh_init(const float* __restrict__ logits, const int* __restrict__ gt) {
    __shared__ float sS[KCLS];
    __shared__ int sB[KCLS];
    __shared__ float sR[JTOT];
    int t = threadIdx.x;
    if (t < KCLS) { sS[t] = 0.f; sB[t] = 0; }
    if (t < JTOT) sR[t] = 0.f;
    __syncthreads();
    int n = blockIdx.x * blockDim.x + t;
    int k = gt[n];
    const float* lr = logits + (size_t)n * JTOT + k * MPROT;
    float v[MPROT]; float sum = 0.f;
    #pragma unroll
    for (int m = 0; m < MPROT; m++) { v[m] = expf(lr[m] * 20.f); sum += v[m]; }
    atomicAdd(&sS[k], sum);
    atomicAdd(&sB[k], 1);
    #pragma unroll
    for (int m = 0; m < MPROT; m++) atomicAdd(&sR[k * MPROT + m], v[m]);
    g_b[n] = 1.f;
    __syncthreads();
    if (t < KCLS) { atomicAdd(&g_S[t], sS[t]); atomicAdd(&g_Bk[t], sB[t]); }
    if (t < JTOT) atomicAdd(&g_R[t], sR[t]);
}

// row-factor update: a <- a / (max(a*R, 1e-12) * M); t=0 bootstraps a from S
__global__ void k_a(int t) {
    int j = threadIdx.x;
    if (j >= JTOT) return;
    int k = j / MPROT;
    float ap = (t == 0) ? 1.f / fmaxf(g_S[k], 1e-12f) : g_a[j];
    float rowsum = ap * g_R[t * JTOT + j];
    g_a[j] = ap / (fmaxf(rowsum, 1e-12f) * (float)MPROT);
}

// col-factor update (b) + accumulate next-iteration row sums R[slot]
__global__ void k_bR(const float* __restrict__ logits, const int* __restrict__ gt, int slot) {
    __shared__ float sR[JTOT];
    int t = threadIdx.x;
    if (t < JTOT) sR[t] = 0.f;
    __syncthreads();
    int n = blockIdx.x * blockDim.x + t;
    int k = gt[n];
    const float* lr = logits + (size_t)n * JTOT + k * MPROT;
    float v[MPROT], a[MPROT]; float s = 0.f;
    #pragma unroll
    for (int m = 0; m < MPROT; m++) {
        v[m] = expf(lr[m] * 20.f);
        a[m] = __ldg(&g_a[k * MPROT + m]);
        s = fmaf(v[m], a[m], s);
    }
    float b = g_b[n];
    float col = b * s;
    float Bk = fmaxf((float)g_Bk[k], 1.f);
    float nb = (col > 0.f) ? (b / fmaxf(col, 1e-12f)) / Bk : 0.f;
    g_b[n] = nb;
    #pragma unroll
    for (int m = 0; m < MPROT; m++) atomicAdd(&sR[k * MPROT + m], v[m] * nb);
    __syncthreads();
    if (t < JTOT) atomicAdd(&g_R[slot * JTOT + t], sR[t]);
}

// final: per-pixel argmax_m v*a -> index + proto_target
__global__ void k_final(const float* __restrict__ logits, const int* __restrict__ gt,
                        float* __restrict__ target) {
    int n = blockIdx.x * blockDim.x + threadIdx.x;
    int k = gt[n];
    const float* lr = logits + (size_t)n * JTOT + k * MPROT;
    float best = -FLT_MAX; int bm = 0;
    #pragma unroll
    for (int m = 0; m < MPROT; m++) {
        float q = expf(lr[m] * 20.f) * __ldg(&g_a[k * MPROT + m]);
        if (q > best) { best = q; bm = m; }
    }
    g_m[n] = (unsigned char)bm;
    target[n] = (float)(bm + MPROT * k);
}

// accumulate f[k,m,:] over correct pixels
__global__ void k_faccum(const int* __restrict__ gt) {
    int t = threadIdx.x;
    int base = blockIdx.x * 32;
    for (int p = 0; p < 32; p++) {
        int n = base + p;
        if (!g_corr[n]) continue;
        int j = gt[n] * MPROT + g_m[n];
        if (t == 0) atomicAdd(&g_cnt[j], 1);
        for (int d = t; d < DIMC; d += blockDim.x)
            atomicAdd(&g_f[j * DIMC + d], g_cn[(size_t)d * NPIX + n]);
    }
}

// prototype EMA update + final l2 normalize
__global__ void k_proto_out(float* __restrict__ outp) {
    __shared__ float red[256];
    __shared__ float cand[DIMC];
    int j = blockIdx.x, t = threadIdx.x, k = j / MPROT;
    int cnt = g_cnt[j];
    int rs = 0;
    #pragma unroll
    for (int m = 0; m < MPROT; m++) rs += g_cnt[k * MPROT + m];
    bool upd = (cnt > 0) && (rs > 0);
    float ss = 0.f;
    for (int d = t; d < DIMC; d += 256) { float fv = g_f[j * DIMC + d]; ss += fv * fv; }
    float fn = sqrtf(block_reduce_256(ss, red));
    float finv = 1.f / fmaxf(fn, 1e-12f);
    float ss2 = 0.f;
    for (int d = t; d < DIMC; d += 256) {
        float p = g_Pn[j * DIMC + d];
        float cv = upd ? (0.999f * p + 0.001f * (g_f[j * DIMC + d] * finv)) : p;
        cand[d] = cv; ss2 += cv * cv;
    }
    float n2 = fmaxf(sqrtf(block_reduce_256(ss2, red)), 1e-12f);
    float inv2 = 1.f / n2;
    __syncthreads();
    for (int d = t; d < DIMC; d += 256) outp[j * DIMC + d] = cand[d] * inv2;
}

// ---------------- launch ----------------
extern "C" void kernel_launch(void* const* d_in, const int* in_sizes, int n_in,
                              void* d_out, int out_size) {
    const float* c  = (const float*)d_in[0];
    const int*   gt = (const int*)d_in[1];
    const float* P  = (const float*)d_in[2];
    const float* fg = (const float*)d_in[3];
    const float* fb = (const float*)d_in[4];
    const float* mg = (const float*)d_in[5];
    const float* mb = (const float*)d_in[6];

    float* out      = (float*)d_out;
    float* out_seg  = out;                              // 2,490,368
    float* logits   = out + 2490368;                    // 24,903,680
    float* target   = out + 2490368 + 24903680;         // 131,072
    float* pnew     = target + NPIX;                    // 136,800

    k_zero<<<535, 256>>>();
    k_prep_scal<<<1, 256>>>(fg, fb);
    k_prep_protos<<<JTOT, 256>>>(P);
    k_stats<<<NPIX / 256, 256>>>(c, fg, fb);
    k_normwrite<<<(DIMC * NPIX / 4) / 256, 256>>>(c, fg, fb);
    k_gemm<<<NPIX / 64, 256>>>(logits);
    k_head<<<NPIX / 8, 256>>>(logits, gt, mg, mb, out_seg);
    k_sh_init<<<NPIX / 256, 256>>>(logits, gt);
    k_a<<<1, 192>>>(0);
    k_bR<<<NPIX / 256, 256>>>(logits, gt, 1);
    k_a<<<1, 192>>>(1);
    k_bR<<<NPIX / 256, 256>>>(logits, gt, 2);
    k_a<<<1, 192>>>(2);
    k_final<<<NPIX / 256, 256>>>(logits, gt, target);
    k_faccum<<<NPIX / 32, 256>>>(gt);
    k_proto_out<<<JTOT, 256>>>(pnew);
}